// round 4
// baseline (speedup 1.0000x reference)
#include <cuda_runtime.h>

// Problem constants
#define BB     128
#define NNODE  512
#define KD     512          // IN == HID == 512 (contraction dim)
#define HD     512
#define JD     3072         // 1536 bilinear (g,p,r) + 1536 linear (g,h)
#define NTOT   (BB * NNODE) // 65536 nodes

// GEMM tile config (fp32 SIMT)
#define BM     64
#define BN     128
#define BKT    16
#define NCTA   148

// ---------------- device globals (no runtime allocation allowed) -------------
__device__ float g_left[(size_t)NTOT * JD];   // precomputed left projections, by node id
__device__ float g_rw[(size_t)NTOT * JD];     // right projections, by worklist position
__device__ float g_c[(size_t)NTOT * HD];      // cell state, by node id
__device__ float g_wlt[KD * JD];              // Wleft  transposed [k][j]
__device__ float g_wrt[KD * JD];              // Wright transposed [k][j]
__device__ unsigned short g_lvl[NTOT];
__device__ int g_count[NNODE];
__device__ int g_off[NNODE + 1];
__device__ int g_cursor[NNODE];
__device__ int g_nlev;
__device__ unsigned g_nodeid[NTOT];           // worklist: flat node id b*N+t
__device__ int g_parid[NTOT];                 // worklist: flat parent id, -1 = root
__device__ unsigned g_bar_count;              // grid barrier (self-resetting)
__device__ unsigned g_bar_epoch;              // monotonic across replays

// ---------------- weight packing --------------------------------------------
// Wleft rows j<1536: wl flattened (g,p,r) -> exactly wl[j][k]; rows >=1536: ul[(j-1536)][k]
// Same structure for Wright with wr / ur. Stored transposed [k][j] for coalesced B loads.
__global__ void pack_weights_k(const float* __restrict__ wl, const float* __restrict__ ul,
                               const float* __restrict__ wr, const float* __restrict__ ur) {
    int idx = blockIdx.x * blockDim.x + threadIdx.x;
    if (idx >= KD * JD) return;
    int k = idx / JD, j = idx % JD;
    g_wlt[idx] = (j < 1536) ? wl[(size_t)j * KD + k] : ul[(size_t)(j - 1536) * KD + k];
    g_wrt[idx] = (j < 1536) ? wr[(size_t)j * KD + k] : ur[(size_t)(j - 1536) * KD + k];
}

// ---------------- level decomposition ----------------------------------------
__global__ void build_levels_k(const int* __restrict__ parent) {
    int tid = threadIdx.x;
    if (tid < NNODE) { g_count[tid] = 0; g_cursor[tid] = 0; }
    if (tid == 0) g_nlev = 0;
    __syncthreads();
    if (tid < BB) {
        int base = tid * NNODE;
        g_lvl[base] = 0;
        atomicAdd(&g_count[0], 1);
        int mx = 0;
        for (int t = 1; t < NNODE; t++) {
            int p = parent[base + t];          // guaranteed p < t
            int L = (int)g_lvl[base + p] + 1;
            g_lvl[base + t] = (unsigned short)L;
            atomicAdd(&g_count[L], 1);
            if (L > mx) mx = L;
        }
        atomicMax(&g_nlev, mx + 1);
    }
    __syncthreads();
    if (tid == 0) {
        int s = 0;
        for (int l = 0; l < NNODE; l++) { g_off[l] = s; s += g_count[l]; }
        g_off[NNODE] = s;
    }
    __syncthreads();
    if (tid < BB) {
        int base = tid * NNODE;
        for (int t = 0; t < NNODE; t++) {
            int L = g_lvl[base + t];
            int pos = g_off[L] + atomicAdd(&g_cursor[L], 1);
            g_nodeid[pos] = (unsigned)(base + t);
            g_parid[pos]  = (t == 0) ? -1 : (base + parent[base + t]);
        }
    }
}

// ---------------- shared GEMM tile (64x128, K-step 16, 256 threads) ----------
// C[r][col0+...] (+)= A[r][:] @ Bt[:][col0+...].  GATHER: A rows come from
// h_buf[par[r]] (par<0 or r>=M -> zero row).
template<bool GATHER>
__device__ __forceinline__ void gemm_tile(
    const float* Asrc, const int* rowpar, int M,
    const float* __restrict__ Bt, float* Cout, int tm, int tn) {
    __shared__ float As[BKT][BM + 4];
    __shared__ float Bs[BKT][BN];
    int tid = threadIdx.x;
    int tx = tid & 15, ty = tid >> 4;
    int row0 = tm * BM, col0 = tn * BN;

    float acc[4][8];
#pragma unroll
    for (int m = 0; m < 4; m++)
#pragma unroll
        for (int n = 0; n < 8; n++) acc[m][n] = 0.f;

    int arow = tid >> 2;
    int akq  = (tid & 3) * 4;
    const float* aptr = nullptr;
    {
        int r = row0 + arow;
        if (GATHER) {
            int p = (r < M) ? rowpar[r] : -1;
            if (p >= 0) aptr = Asrc + (size_t)p * KD;
        } else {
            if (r < M) aptr = Asrc + (size_t)r * KD;
        }
    }

    for (int k0 = 0; k0 < KD; k0 += BKT) {
        float4 av = make_float4(0.f, 0.f, 0.f, 0.f);
        if (aptr) av = *(const float4*)(aptr + k0 + akq);
        As[akq + 0][arow] = av.x;
        As[akq + 1][arow] = av.y;
        As[akq + 2][arow] = av.z;
        As[akq + 3][arow] = av.w;
#pragma unroll
        for (int i = 0; i < 2; i++) {
            int f  = tid + i * 256;
            int bk = f >> 5;
            int c4 = (f & 31) * 4;
            *(float4*)&Bs[bk][c4] = *(const float4*)(Bt + (size_t)(k0 + bk) * JD + col0 + c4);
        }
        __syncthreads();
#pragma unroll
        for (int k = 0; k < BKT; k++) {
            float a[4], b[8];
            *(float4*)a       = *(const float4*)&As[k][ty * 4];
            *(float4*)b       = *(const float4*)&Bs[k][tx * 8];
            *(float4*)(b + 4) = *(const float4*)&Bs[k][tx * 8 + 4];
#pragma unroll
            for (int m = 0; m < 4; m++)
#pragma unroll
                for (int n = 0; n < 8; n++) acc[m][n] = fmaf(a[m], b[n], acc[m][n]);
        }
        __syncthreads();
    }

#pragma unroll
    for (int m = 0; m < 4; m++) {
        int r = row0 + ty * 4 + m;
        if (r < M) {
            float* cp = Cout + (size_t)r * JD + col0 + tx * 8;
            *(float4*)cp       = make_float4(acc[m][0], acc[m][1], acc[m][2], acc[m][3]);
            *(float4*)(cp + 4) = make_float4(acc[m][4], acc[m][5], acc[m][6], acc[m][7]);
        }
    }
}

// ---------------- left projection GEMM (fully parallel) ----------------------
__global__ __launch_bounds__(256) void left_gemm_k(const float* __restrict__ emb) {
    gemm_tile<false>(emb, nullptr, NTOT, g_wlt, g_left, blockIdx.y, blockIdx.x);
}

// ---------------- grid barrier ----------------------------------------------
__device__ __forceinline__ void grid_barrier(unsigned target) {
    __syncthreads();
    if (threadIdx.x == 0) {
        __threadfence();
        unsigned arrived = atomicAdd(&g_bar_count, 1);
        if (arrived == gridDim.x - 1) {
            atomicExch(&g_bar_count, 0);
            __threadfence();
            atomicExch(&g_bar_epoch, target);
        } else {
            while (atomicAdd(&g_bar_epoch, 0u) < target) { __nanosleep(64); }
        }
    }
    __syncthreads();
}

// ---------------- persistent level-sweep kernel -------------------------------
__global__ __launch_bounds__(256) void tree_lstm_k(float* hout,
                                                   const float* __restrict__ wo,
                                                   const float* __restrict__ bias) {
    __shared__ float pooled_s[8][24];
    unsigned epoch = g_bar_epoch;   // carries across graph replays; uniform at entry
    int nlev = g_nlev;
    int warp = threadIdx.x >> 5, lane = threadIdx.x & 31;
    int gw = blockIdx.x * 8 + warp;
    int nw = gridDim.x * 8;

    for (int lvl = 0; lvl < nlev; lvl++) {
        int base = g_off[lvl];
        int M    = g_off[lvl + 1] - base;

        // Phase 1: RW[M x 3072] = gather(h[parent]) @ Wright^T
        int ntn = JD / BN;
        int ntiles = ((M + BM - 1) / BM) * ntn;
        for (int tile = blockIdx.x; tile < ntiles; tile += gridDim.x) {
            gemm_tile<true>(hout, g_parid + base, M, g_wrt,
                            g_rw + (size_t)base * JD, tile / ntn, tile % ntn);
        }
        epoch++; grid_barrier(epoch);

        // Phase 2: per-node epilogue (warp per node)
        for (int i = gw; i < M; i += nw) {
            unsigned nid = g_nodeid[base + i];
            int pidx = g_parid[base + i];
            const float* Lrow = g_left + (size_t)nid * JD;
            const float* Rrow = g_rw + (size_t)(base + i) * JD;

            // pooled[g,p] = sum_r lw * rw   (24 pairs x 64 ranks)
#pragma unroll
            for (int gp = 0; gp < 24; gp++) {
                int o = gp * 64 + lane;
                float v = Lrow[o] * Rrow[o] + Lrow[o + 32] * Rrow[o + 32];
#pragma unroll
                for (int s = 16; s > 0; s >>= 1) v += __shfl_xor_sync(0xffffffffu, v, s);
                if (lane == 0) pooled_s[warp][gp] = v;
            }
            __syncwarp();

            for (int hh = lane; hh < HD; hh += 32) {
                float gv[3];
#pragma unroll
                for (int g = 0; g < 3; g++) {
                    float acc = bias[g * HD + hh] + Lrow[1536 + g * HD + hh]
                              + Rrow[1536 + g * HD + hh];
                    const float* wop = wo + (size_t)(g * HD + hh) * 8;
#pragma unroll
                    for (int p = 0; p < 8; p++) acc = fmaf(pooled_s[warp][g * 8 + p], wop[p], acc);
                    gv[g] = acc;
                }
                float f  = 1.f / (1.f + expf(-gv[0]));
                float o_ = 1.f / (1.f + expf(-gv[1]));
                float z  = tanhf(gv[2]);
                float pc = (pidx >= 0) ? g_c[(size_t)pidx * HD + hh] : 0.f;
                float c  = pc * f + (1.f - f) * z;
                float h  = o_ * tanhf(c);
                g_c[(size_t)nid * HD + hh]  = c;
                hout[(size_t)nid * HD + hh] = h;
            }
            __syncwarp();   // pooled_s reuse
        }
        epoch++; grid_barrier(epoch);
    }
}

// ---------------- launch ------------------------------------------------------
extern "C" void kernel_launch(void* const* d_in, const int* in_sizes, int n_in,
                              void* d_out, int out_size) {
    const float* emb    = (const float*)d_in[0];
    const int*   parent = (const int*)d_in[1];
    // d_in[2] = node_mask (unused, all ones)
    const float* wl   = (const float*)d_in[3];
    const float* wr   = (const float*)d_in[4];
    const float* wo   = (const float*)d_in[5];
    const float* ul   = (const float*)d_in[6];
    const float* ur   = (const float*)d_in[7];
    const float* bias = (const float*)d_in[8];
    float* hout = (float*)d_out;

    pack_weights_k<<<(KD * JD + 255) / 256, 256>>>(wl, ul, wr, ur);
    build_levels_k<<<1, 512>>>(parent);
    left_gemm_k<<<dim3(JD / BN, NTOT / BM), 256>>>(emb);
    tree_lstm_k<<<NCTA, 256>>>(hout, wo, bias);
}

// round 7
// speedup vs baseline: 1.8712x; 1.8712x over previous
#include <cuda_runtime.h>
#include <cstdint>

// Problem constants
#define BB     128
#define NNODE  512
#define KD     512          // IN == HID == 512 (contraction dim)
#define HD     512
#define JD     3072         // 1536 bilinear (g,p,r) + 1536 linear (g,h)
#define NTOT   (BB * NNODE) // 65536 nodes

// SIMT GEMM tile config
#define BM     64
#define BN     128
#define BKT    16
#define NCTA   148

// Left tensor-core GEMM tile
#define LTM    128
#define LTN    128
#define LKC    32                 // K elements per chunk = 128 bytes (tf32)
#define LCHUNKS (KD / LKC)        // 16
// idesc: dtype F32=1 @bit4, atype TF32=2 @bit7, btype TF32=2 @bit10, N/8 @bit17, M/16 @bit24
#define LIDESC ((1u << 4) | (2u << 7) | (2u << 10) | ((LTN / 8u) << 17) | ((LTM / 16u) << 24))

// tcgen05 is only legal in the arch-SPECIFIC (sm_103a) compilation pass. The
// harness also runs a plain compute_103 ptxas pass, which rejects tcgen05
// outright — so every tcgen05 token must vanish from that pass.
#if defined(__CUDA_ARCH_FEAT_SM103_ALL) || defined(__CUDA_ARCH_FEAT_SM100_ALL) || \
    (defined(__CUDA_ARCH_SPECIFIC__) && (__CUDA_ARCH_SPECIFIC__ == 1030))
#define HAS_TCGEN05 1
#else
#define HAS_TCGEN05 0
#endif

// ---------------- device globals (no runtime allocation allowed) -------------
__device__ float g_left[(size_t)NTOT * JD];   // left projections, by node id
__device__ float g_rw[(size_t)NTOT * JD];     // right projections, BY NODE ID (dedup)
__device__ float g_c[(size_t)NTOT * HD];      // cell state, by node id
__device__ float g_wlt[KD * JD];              // Wleft  transposed [k][j] (SIMT fallback)
__device__ float g_wrt[KD * JD];              // Wright transposed [k][j]
__device__ unsigned short g_lvl[NTOT];
__device__ unsigned char g_haschild[NTOT];
__device__ int g_count[NNODE];
__device__ int g_off[NNODE + 1];
__device__ int g_cursor[NNODE];
__device__ int g_icount[NNODE];
__device__ int g_ioff[NNODE + 1];
__device__ int g_icursor[NNODE];
__device__ int g_nlev;
__device__ unsigned g_nodeid[NTOT];           // worklist: flat node id b*N+t
__device__ int g_parid[NTOT];                 // worklist: flat parent id, -1 = root
__device__ int g_iwork[NTOT];                 // internal-node worklist (by level)
__device__ unsigned g_bar_count;              // grid barrier (self-resetting)
__device__ unsigned g_bar_epoch;              // monotonic across replays

// ---------------- generic PTX helpers (legal on all passes) -------------------
__device__ __forceinline__ uint32_t smem_u32(const void* p) {
    uint32_t a;
    asm("{ .reg .u64 t; cvta.to.shared.u64 t, %1; cvt.u32.u64 %0, t; }" : "=r"(a) : "l"(p));
    return a;
}
#define SMEM_SWIZZLE_128B(o) ((o) ^ (((o) >> 3) & 0x70))

#if HAS_TCGEN05
__device__ __forceinline__ uint32_t elect_one_pred() {
    uint32_t p;
    asm volatile("{ .reg .pred p; elect.sync _|p, 0xFFFFFFFF; selp.b32 %0, 1, 0, p; }" : "=r"(p));
    return p;
}
__device__ __forceinline__ uint32_t to_tf32(float x) {
    uint32_t r; asm("cvt.rna.tf32.f32 %0, %1;" : "=r"(r) : "f"(x)); return r;
}

static constexpr uint64_t SMEM_DESC_BASE_SW128 =
    (uint64_t(2) << 61) | (uint64_t(1) << 46) | (uint64_t(64) << 32) | (uint64_t(1) << 16);
#define MAKE_SMEM_DESC(base) (SMEM_DESC_BASE_SW128 | ((uint64_t)((base) >> 4) & 0x3FFF))

#define TCGEN05_ALLOC(sres, n) \
    asm volatile("tcgen05.alloc.cta_group::1.sync.aligned.shared::cta.b32 [%0], %1;" \
                 :: "r"((uint32_t)(sres)), "r"((uint32_t)(n)) : "memory")
#define TCGEN05_DEALLOC(t, n) \
    asm volatile("tcgen05.dealloc.cta_group::1.sync.aligned.b32 %0, %1;" :: "r"(t), "r"((uint32_t)(n)))
#define TCGEN05_RELINQ() \
    asm volatile("tcgen05.relinquish_alloc_permit.cta_group::1.sync.aligned;")
#define TCGEN05_COMMIT(mb) \
    asm volatile("tcgen05.commit.cta_group::1.mbarrier::arrive::one.shared::cluster.b64 [%0];" \
                 :: "r"((uint32_t)(mb)) : "memory")
#define TCGEN05_FENCE_AFTER()  asm volatile("tcgen05.fence::after_thread_sync;" ::: "memory")
#define TCGEN05_FENCE_BEFORE() asm volatile("tcgen05.fence::before_thread_sync;" ::: "memory")
#define TCGEN05_WAIT_LD()      asm volatile("tcgen05.wait::ld.sync.aligned;" ::: "memory")
#define FENCE_PROXY_ASYNC()    asm volatile("fence.proxy.async.shared::cta;" ::: "memory")
#define MBARRIER_INIT(mb, c) \
    asm volatile("mbarrier.init.shared.b64 [%0], %1;" :: "r"((uint32_t)(mb)), "r"((uint32_t)(c)) : "memory")
#define MBARRIER_WAIT_PARITY(mb, ph) do { \
    uint32_t _m = (uint32_t)(mb), _p = (uint32_t)(ph), _d; \
    asm volatile("{ .reg .pred p; mbarrier.try_wait.parity.acquire.cta.shared::cta.b64 p, [%1], %2; selp.b32 %0, 1, 0, p; }" \
                 : "=r"(_d) : "r"(_m), "r"(_p) : "memory"); \
    if (!_d) { \
        asm volatile("{ .reg .pred P1; WL_%=: mbarrier.try_wait.parity.acquire.cta.shared::cta.b64 P1, [%0], %1, 0x989680; @P1 bra.uni WD_%=; bra.uni WL_%=; WD_%=: }" \
                     :: "r"(_m), "r"(_p) : "memory"); \
    } } while (0)

#define TCGEN05_LD_32X32B_X32(r, addr) \
    asm volatile("tcgen05.ld.sync.aligned.32x32b.x32.b32 " \
        "{%0, %1, %2, %3, %4, %5, %6, %7, %8, %9, %10, %11, %12, %13, %14, %15, " \
        " %16, %17, %18, %19, %20, %21, %22, %23, %24, %25, %26, %27, %28, %29, %30, %31}, [%32];" \
        : "=r"((r)[0]),  "=r"((r)[1]),  "=r"((r)[2]),  "=r"((r)[3]), \
          "=r"((r)[4]),  "=r"((r)[5]),  "=r"((r)[6]),  "=r"((r)[7]), \
          "=r"((r)[8]),  "=r"((r)[9]),  "=r"((r)[10]), "=r"((r)[11]), \
          "=r"((r)[12]), "=r"((r)[13]), "=r"((r)[14]), "=r"((r)[15]), \
          "=r"((r)[16]), "=r"((r)[17]), "=r"((r)[18]), "=r"((r)[19]), \
          "=r"((r)[20]), "=r"((r)[21]), "=r"((r)[22]), "=r"((r)[23]), \
          "=r"((r)[24]), "=r"((r)[25]), "=r"((r)[26]), "=r"((r)[27]), \
          "=r"((r)[28]), "=r"((r)[29]), "=r"((r)[30]), "=r"((r)[31]) \
        : "r"(addr))

__device__ __forceinline__ void mma_tf32_ss(uint32_t d, uint64_t ad, uint64_t bd,
                                            uint32_t idesc, bool acc) {
    uint32_t en = acc ? 1u : 0u, z = 0u;
    asm volatile(
        "{\n\t.reg .pred p;\n\tsetp.ne.u32 p, %6, 0;\n\t"
        "tcgen05.mma.cta_group::1.kind::tf32 [%0], %1, %2, %3, {%4, %4, %4, %4}, p;\n\t}"
        :: "r"(d), "l"(ad), "l"(bd), "r"(idesc), "r"(z), "r"(z), "r"(en) : "memory");
}
#endif  // HAS_TCGEN05

// ---------------- weight packing ----------------------------------------------
__global__ void pack_weights_k(const float* __restrict__ wl, const float* __restrict__ ul,
                               const float* __restrict__ wr, const float* __restrict__ ur) {
    int idx = blockIdx.x * blockDim.x + threadIdx.x;
    if (idx >= KD * JD) return;
    int k = idx / JD, j = idx % JD;
    g_wlt[idx] = (j < 1536) ? wl[(size_t)j * KD + k] : ul[(size_t)(j - 1536) * KD + k];
    g_wrt[idx] = (j < 1536) ? wr[(size_t)j * KD + k] : ur[(size_t)(j - 1536) * KD + k];
}

// ---------------- level decomposition ----------------------------------------
__global__ void build_levels_k(const int* __restrict__ parent) {
    int tid = threadIdx.x;
    if (tid < NNODE) { g_count[tid] = 0; g_cursor[tid] = 0; g_icount[tid] = 0; g_icursor[tid] = 0; }
    if (tid == 0) g_nlev = 0;
    __syncthreads();
    if (tid < BB) {
        int base = tid * NNODE;
        for (int t = 0; t < NNODE; t++) g_haschild[base + t] = 0;
    }
    __syncthreads();
    if (tid < BB) {
        int base = tid * NNODE;
        g_lvl[base] = 0;
        atomicAdd(&g_count[0], 1);
        int mx = 0;
        for (int t = 1; t < NNODE; t++) {
            int p = parent[base + t];          // guaranteed p < t
            int L = (int)g_lvl[base + p] + 1;
            g_lvl[base + t] = (unsigned short)L;
            atomicAdd(&g_count[L], 1);
            g_haschild[base + p] = 1;
            if (L > mx) mx = L;
        }
        atomicMax(&g_nlev, mx + 1);
    }
    __syncthreads();
    if (tid < BB) {
        int base = tid * NNODE;
        for (int t = 0; t < NNODE; t++)
            if (g_haschild[base + t]) atomicAdd(&g_icount[g_lvl[base + t]], 1);
    }
    __syncthreads();
    if (tid == 0) {
        int s = 0, si = 0;
        for (int l = 0; l < NNODE; l++) {
            g_off[l] = s;  s  += g_count[l];
            g_ioff[l] = si; si += g_icount[l];
        }
        g_off[NNODE] = s; g_ioff[NNODE] = si;
    }
    __syncthreads();
    if (tid < BB) {
        int base = tid * NNODE;
        for (int t = 0; t < NNODE; t++) {
            int L = g_lvl[base + t];
            int pos = g_off[L] + atomicAdd(&g_cursor[L], 1);
            g_nodeid[pos] = (unsigned)(base + t);
            g_parid[pos]  = (t == 0) ? -1 : (base + parent[base + t]);
            if (g_haschild[base + t]) {
                int ip = g_ioff[L] + atomicAdd(&g_icursor[L], 1);
                g_iwork[ip] = base + t;
            }
        }
    }
}

// ---------------- shared SIMT GEMM tile (64x128, K-step 16, 256 threads) ------
// C[outrow(r)][col0+...] = A[rows(r)][:] @ Bt[:][col0+...]
template<bool GATHER>
__device__ __forceinline__ void gemm_tile(
    const float* Asrc, const int* rows, int M,
    const float* __restrict__ Bt, float* Cout, const int* outrows, int tm, int tn) {
    __shared__ float As[BKT][BM + 4];
    __shared__ float Bs[BKT][BN];
    int tid = threadIdx.x;
    int tx = tid & 15, ty = tid >> 4;
    int row0 = tm * BM, col0 = tn * BN;

    float acc[4][8];
#pragma unroll
    for (int m = 0; m < 4; m++)
#pragma unroll
        for (int n = 0; n < 8; n++) acc[m][n] = 0.f;

    int arow = tid >> 2;
    int akq  = (tid & 3) * 4;
    const float* aptr = nullptr;
    {
        int r = row0 + arow;
        if (GATHER) {
            int p = (r < M) ? rows[r] : -1;
            if (p >= 0) aptr = Asrc + (size_t)p * KD;
        } else {
            if (r < M) aptr = Asrc + (size_t)r * KD;
        }
    }

    for (int k0 = 0; k0 < KD; k0 += BKT) {
        float4 av = make_float4(0.f, 0.f, 0.f, 0.f);
        if (aptr) av = *(const float4*)(aptr + k0 + akq);
        As[akq + 0][arow] = av.x;
        As[akq + 1][arow] = av.y;
        As[akq + 2][arow] = av.z;
        As[akq + 3][arow] = av.w;
#pragma unroll
        for (int i = 0; i < 2; i++) {
            int f  = tid + i * 256;
            int bk = f >> 5;
            int c4 = (f & 31) * 4;
            *(float4*)&Bs[bk][c4] = *(const float4*)(Bt + (size_t)(k0 + bk) * JD + col0 + c4);
        }
        __syncthreads();
#pragma unroll
        for (int k = 0; k < BKT; k++) {
            float a[4], b[8];
            *(float4*)a       = *(const float4*)&As[k][ty * 4];
            *(float4*)b       = *(const float4*)&Bs[k][tx * 8];
            *(float4*)(b + 4) = *(const float4*)&Bs[k][tx * 8 + 4];
#pragma unroll
            for (int m = 0; m < 4; m++)
#pragma unroll
                for (int n = 0; n < 8; n++) acc[m][n] = fmaf(a[m], b[n], acc[m][n]);
        }
        __syncthreads();
    }

#pragma unroll
    for (int m = 0; m < 4; m++) {
        int r = row0 + ty * 4 + m;
        if (r < M) {
            int orow = outrows ? outrows[r] : r;
            float* cp = Cout + (size_t)orow * JD + col0 + tx * 8;
            *(float4*)cp       = make_float4(acc[m][0], acc[m][1], acc[m][2], acc[m][3]);
            *(float4*)(cp + 4) = make_float4(acc[m][4], acc[m][5], acc[m][6], acc[m][7]);
        }
    }
}

// ---------------- LEFT projection GEMM ----------------------------------------
// out[node, j] = sum_k emb[node,k] * W[j,k], W rows = wl (j<1536) / ul (j>=1536).
// sm_103a pass: tcgen05 tf32 SS MMA. Other passes: SIMT fallback (correct, slower).
__global__ __launch_bounds__(256) void left_tc_k(const float* __restrict__ emb,
                                                 const float* __restrict__ wl,
                                                 const float* __restrict__ ul) {
#if HAS_TCGEN05
    __shared__ char rawbuf[2 * LTM * 128 + 1024];   // A tile + B tile, 1024B-aligned
    __shared__ uint32_t s_tmem;
    __shared__ __align__(8) unsigned long long s_mbar;

    int tid = threadIdx.x;
    int wid = tid >> 5, lane = tid & 31;
    int row0 = blockIdx.y * LTM;      // node rows
    int col0 = blockIdx.x * LTN;      // j cols

    uint32_t raw = smem_u32(rawbuf);
    uint32_t aBase = (raw + 1023u) & ~1023u;
    uint32_t bBase = aBase + LTM * 128;
    char* aPtr = rawbuf + (aBase - raw);
    char* bPtr = aPtr + LTM * 128;
    uint32_t mb = smem_u32(&s_mbar);
    uint32_t tp = smem_u32(&s_tmem);

    if (wid == 0) { TCGEN05_ALLOC(tp, 128); TCGEN05_RELINQ(); }
    if (tid == 0) MBARRIER_INIT(mb, 1);
    __syncthreads();
    uint32_t tmem;
    asm volatile("ld.shared.b32 %0, [%1];" : "=r"(tmem) : "r"(tp));

    uint64_t ad = MAKE_SMEM_DESC(aBase);
    uint64_t bd = MAKE_SMEM_DESC(bBase);

    for (int c = 0; c < LCHUNKS; c++) {
        if (c > 0) MBARRIER_WAIT_PARITY(mb, (c - 1) & 1);   // prior MMA done reading SMEM
        int kc0 = c * LKC;
        // A chunk: 128 rows x 32 tf32 (128B/row), SW128 swizzled; 256 thr x 4 iters
#pragma unroll
        for (int i = 0; i < 4; i++) {
            int f = tid + (i << 8);
            int row = f >> 3, seg = f & 7;
            float4 v = *(const float4*)(emb + (size_t)(row0 + row) * KD + kc0 + seg * 4);
            uint4 t = make_uint4(to_tf32(v.x), to_tf32(v.y), to_tf32(v.z), to_tf32(v.w));
            *(uint4*)(aPtr + SMEM_SWIZZLE_128B(row * 128 + seg * 16)) = t;
        }
        // B chunk: 128 j-rows x 32 tf32
#pragma unroll
        for (int i = 0; i < 4; i++) {
            int f = tid + (i << 8);
            int row = f >> 3, seg = f & 7;
            int j = col0 + row;
            const float* src = (j < 1536) ? (wl + (size_t)j * KD) : (ul + (size_t)(j - 1536) * KD);
            float4 v = *(const float4*)(src + kc0 + seg * 4);
            uint4 t = make_uint4(to_tf32(v.x), to_tf32(v.y), to_tf32(v.z), to_tf32(v.w));
            *(uint4*)(bPtr + SMEM_SWIZZLE_128B(row * 128 + seg * 16)) = t;
        }
        __syncthreads();
        FENCE_PROXY_ASYNC();
        if (wid == 0) {
            if (elect_one_pred()) {
#pragma unroll
                for (int s = 0; s < 4; s++)   // 4 K-steps of 8 tf32 (32B desc stride = +2)
                    mma_tf32_ss(tmem, ad + s * 2, bd + s * 2, LIDESC, (c > 0) || (s > 0));
                TCGEN05_COMMIT(mb);
            }
        }
    }
    MBARRIER_WAIT_PARITY(mb, (LCHUNKS - 1) & 1);
    TCGEN05_FENCE_AFTER();

    // Read D (128x128 fp32): warps 0-3 own the four 32-lane subpartitions
    if (wid < 4) {
        int r = row0 + wid * 32 + lane;
        float* dst0 = g_left + (size_t)r * JD + col0;
#pragma unroll
        for (int cb = 0; cb < LTN; cb += 32) {
            uint32_t d[32];
            TCGEN05_LD_32X32B_X32(d, tmem + cb);
            TCGEN05_WAIT_LD();
#pragma unroll
            for (int j = 0; j < 32; j++) dst0[cb + j] = __uint_as_float(d[j]);
        }
        TCGEN05_FENCE_BEFORE();
    }
    __syncthreads();
    if (wid == 0) TCGEN05_DEALLOC(tmem, 128);
#else
    // SIMT fallback: two 64-row halves of the 128x128 tile via the shared helper.
    for (int half = 0; half < 2; half++) {
        int rowbase = blockIdx.y * LTM + half * BM;
        gemm_tile<false>(emb + (size_t)rowbase * KD, nullptr, BM, g_wlt,
                         g_left + (size_t)rowbase * JD, nullptr, 0, blockIdx.x);
        __syncthreads();
    }
#endif
}

// ---------------- grid barrier ----------------------------------------------
__device__ __forceinline__ void grid_barrier(unsigned target) {
    __syncthreads();
    if (threadIdx.x == 0) {
        __threadfence();
        unsigned arrived = atomicAdd(&g_bar_count, 1);
        if (arrived == gridDim.x - 1) {
            atomicExch(&g_bar_count, 0);
            __threadfence();
            atomicExch(&g_bar_epoch, target);
        } else {
            while (atomicAdd(&g_bar_epoch, 0u) < target) { __nanosleep(64); }
        }
    }
    __syncthreads();
}

// ---------------- persistent level-sweep kernel -------------------------------
// Per level L: (A) epilogue for all L-nodes (reads g_rw[parent], computed when the
// parent's level ran phase B); (B) right-GEMM for INTERNAL L-nodes only:
// g_rw[nid] = h[nid] @ Wright^T  (dedup: one row per parent instead of per child).
__global__ __launch_bounds__(256) void tree_lstm_k(float* hout,
                                                   const float* __restrict__ wo,
                                                   const float* __restrict__ bias) {
    __shared__ float pooled_s[8][24];
    unsigned epoch = g_bar_epoch;   // carries across graph replays; uniform at entry
    int nlev = g_nlev;
    int warp = threadIdx.x >> 5, lane = threadIdx.x & 31;
    int gw = blockIdx.x * 8 + warp;
    int nw = gridDim.x * 8;
    const int ntn = JD / BN;

    for (int lvl = 0; lvl < nlev; lvl++) {
        int base = g_off[lvl];
        int M    = g_off[lvl + 1] - base;

        // Phase A: per-node epilogue (warp per node)
        for (int i = gw; i < M; i += nw) {
            unsigned nid = g_nodeid[base + i];
            int pidx = g_parid[base + i];
            const float* Lrow = g_left + (size_t)nid * JD;

            if (pidx >= 0) {
                const float* Rrow = g_rw + (size_t)pidx * JD;
                // pooled[g,p] = sum_r lw*rw  (24 pairs x 64 ranks)
#pragma unroll
                for (int gp = 0; gp < 24; gp++) {
                    int o = gp * 64 + lane;
                    float v = Lrow[o] * Rrow[o] + Lrow[o + 32] * Rrow[o + 32];
#pragma unroll
                    for (int s = 16; s > 0; s >>= 1) v += __shfl_xor_sync(0xffffffffu, v, s);
                    if (lane == 0) pooled_s[warp][gp] = v;
                }
                __syncwarp();
                for (int hh = lane; hh < HD; hh += 32) {
                    float gv[3];
#pragma unroll
                    for (int g = 0; g < 3; g++) {
                        float acc = bias[g * HD + hh] + Lrow[1536 + g * HD + hh]
                                  + Rrow[1536 + g * HD + hh];
                        const float* wop = wo + (size_t)(g * HD + hh) * 8;
#pragma unroll
                        for (int p = 0; p < 8; p++) acc = fmaf(pooled_s[warp][g * 8 + p], wop[p], acc);
                        gv[g] = acc;
                    }
                    float f  = 1.f / (1.f + expf(-gv[0]));
                    float o_ = 1.f / (1.f + expf(-gv[1]));
                    float z  = tanhf(gv[2]);
                    float pc = g_c[(size_t)pidx * HD + hh];
                    float c  = pc * f + (1.f - f) * z;
                    float h  = o_ * tanhf(c);
                    g_c[(size_t)nid * HD + hh]  = c;
                    hout[(size_t)nid * HD + hh] = h;
                }
                __syncwarp();   // pooled_s reuse
            } else {
                // root: parent h == 0 -> pooled = 0, right-linear = 0, pc = 0
                for (int hh = lane; hh < HD; hh += 32) {
                    float gv[3];
#pragma unroll
                    for (int g = 0; g < 3; g++)
                        gv[g] = bias[g * HD + hh] + Lrow[1536 + g * HD + hh];
                    float f  = 1.f / (1.f + expf(-gv[0]));
                    float o_ = 1.f / (1.f + expf(-gv[1]));
                    float z  = tanhf(gv[2]);
                    float c  = (1.f - f) * z;
                    float h  = o_ * tanhf(c);
                    g_c[(size_t)nid * HD + hh]  = c;
                    hout[(size_t)nid * HD + hh] = h;
                }
            }
        }
        epoch++; grid_barrier(epoch);

        // Phase B: RW[nid] = h[nid] @ Wright^T for internal nodes at this level
        int ibase = g_ioff[lvl];
        int Mi    = g_ioff[lvl + 1] - ibase;
        if (Mi > 0) {
            int ntiles = ((Mi + BM - 1) / BM) * ntn;
            for (int tile = blockIdx.x; tile < ntiles; tile += gridDim.x) {
                gemm_tile<true>(hout, g_iwork + ibase, Mi, g_wrt,
                                g_rw, g_iwork + ibase, tile / ntn, tile % ntn);
            }
        }
        epoch++; grid_barrier(epoch);
    }
}

// ---------------- launch ------------------------------------------------------
extern "C" void kernel_launch(void* const* d_in, const int* in_sizes, int n_in,
                              void* d_out, int out_size) {
    const float* emb    = (const float*)d_in[0];
    const int*   parent = (const int*)d_in[1];
    // d_in[2] = node_mask (unused, all ones)
    const float* wl   = (const float*)d_in[3];
    const float* wr   = (const float*)d_in[4];
    const float* wo   = (const float*)d_in[5];
    const float* ul   = (const float*)d_in[6];
    const float* ur   = (const float*)d_in[7];
    const float* bias = (const float*)d_in[8];
    float* hout = (float*)d_out;

    pack_weights_k<<<(KD * JD + 255) / 256, 256>>>(wl, ul, wr, ur);
    build_levels_k<<<1, 512>>>(parent);
    left_tc_k<<<dim3(JD / LTN, NTOT / LTM), 256>>>(emb, wl, ul);
    tree_lstm_k<<<NCTA, 256>>>(hout, wo, bias);
}

// round 9
// speedup vs baseline: 2.6655x; 1.4245x over previous
#include <cuda_runtime.h>
#include <cstdint>

// Problem constants
#define BB     128
#define NNODE  512
#define KD     512          // IN == HID == 512 (contraction dim)
#define HD     512
#define JD     3072         // 1536 bilinear (g,p,r) + 1536 linear (g,h)
#define NTOT   (BB * NNODE) // 65536 nodes

// SIMT GEMM tile config (fallback pass only)
#define BM     64
#define BN     128
#define BKT    16

// Persistent kernel shape
#define NCTA   148
#define TLB    512          // threads per block in tree_lstm (16 warps)

// Tensor-core GEMM tile (tf32)
#define LTM    128
#define LTN    128
#define LKC    32                 // K elements per chunk = 128 bytes (tf32)
#define LCHUNKS (KD / LKC)        // 16
#define NTN    (JD / LTN)         // 24 column tiles
// idesc: dtype F32=1 @bit4, atype TF32=2 @bit7, btype TF32=2 @bit10, N/8 @bit17, M/16 @bit24
#define LIDESC ((1u << 4) | (2u << 7) | (2u << 10) | ((LTN / 8u) << 17) | ((LTM / 16u) << 24))

// tcgen05 is only legal in the arch-SPECIFIC (sm_103a) compilation pass. The
// harness also runs a plain compute_103 ptxas pass, which rejects tcgen05
// outright — so every tcgen05 token must vanish from that pass.
#if defined(__CUDA_ARCH_FEAT_SM103_ALL) || defined(__CUDA_ARCH_FEAT_SM100_ALL) || \
    (defined(__CUDA_ARCH_SPECIFIC__) && (__CUDA_ARCH_SPECIFIC__ == 1030))
#define HAS_TCGEN05 1
#else
#define HAS_TCGEN05 0
#endif

// ---------------- device globals (no runtime allocation allowed) -------------
__device__ float g_left[(size_t)NTOT * JD];   // left projections, by node id
__device__ float g_rw[(size_t)NTOT * JD];     // right projections, BY NODE ID (dedup)
__device__ float g_c[(size_t)NTOT * HD];      // cell state, by node id
__device__ float g_wlt[KD * JD];              // Wleft  transposed [k][j] (SIMT fallback)
__device__ float g_wrt[KD * JD];              // Wright transposed [k][j] (SIMT fallback)
__device__ unsigned short g_lvl[NTOT];
__device__ unsigned char g_haschild[NTOT];
__device__ int g_count[NNODE];
__device__ int g_off[NNODE + 1];
__device__ int g_cursor[NNODE];
__device__ int g_icount[NNODE];
__device__ int g_ioff[NNODE + 1];
__device__ int g_icursor[NNODE];
__device__ int g_nlev;
__device__ unsigned g_nodeid[NTOT];           // worklist: flat node id b*N+t
__device__ int g_parid[NTOT];                 // worklist: flat parent id, -1 = root
__device__ int g_iwork[NTOT];                 // internal-node worklist (by level)
__device__ unsigned g_bar_count;              // grid barrier (self-resetting)
__device__ unsigned g_bar_epoch;              // monotonic across replays

// ---------------- generic PTX helpers (legal on all passes) -------------------
__device__ __forceinline__ uint32_t smem_u32(const void* p) {
    uint32_t a;
    asm("{ .reg .u64 t; cvta.to.shared.u64 t, %1; cvt.u32.u64 %0, t; }" : "=r"(a) : "l"(p));
    return a;
}
#define SMEM_SWIZZLE_128B(o) ((o) ^ (((o) >> 3) & 0x70))

#if HAS_TCGEN05
__device__ __forceinline__ uint32_t elect_one_pred() {
    uint32_t p;
    asm volatile("{ .reg .pred p; elect.sync _|p, 0xFFFFFFFF; selp.b32 %0, 1, 0, p; }" : "=r"(p));
    return p;
}
__device__ __forceinline__ uint32_t to_tf32(float x) {
    uint32_t r; asm("cvt.rna.tf32.f32 %0, %1;" : "=r"(r) : "f"(x)); return r;
}

static constexpr uint64_t SMEM_DESC_BASE_SW128 =
    (uint64_t(2) << 61) | (uint64_t(1) << 46) | (uint64_t(64) << 32) | (uint64_t(1) << 16);
#define MAKE_SMEM_DESC(base) (SMEM_DESC_BASE_SW128 | ((uint64_t)((base) >> 4) & 0x3FFF))

#define TCGEN05_ALLOC(sres, n) \
    asm volatile("tcgen05.alloc.cta_group::1.sync.aligned.shared::cta.b32 [%0], %1;" \
                 :: "r"((uint32_t)(sres)), "r"((uint32_t)(n)) : "memory")
#define TCGEN05_DEALLOC(t, n) \
    asm volatile("tcgen05.dealloc.cta_group::1.sync.aligned.b32 %0, %1;" :: "r"(t), "r"((uint32_t)(n)))
#define TCGEN05_RELINQ() \
    asm volatile("tcgen05.relinquish_alloc_permit.cta_group::1.sync.aligned;")
#define TCGEN05_COMMIT(mb) \
    asm volatile("tcgen05.commit.cta_group::1.mbarrier::arrive::one.shared::cluster.b64 [%0];" \
                 :: "r"((uint32_t)(mb)) : "memory")
#define TCGEN05_FENCE_AFTER()  asm volatile("tcgen05.fence::after_thread_sync;" ::: "memory")
#define TCGEN05_FENCE_BEFORE() asm volatile("tcgen05.fence::before_thread_sync;" ::: "memory")
#define TCGEN05_WAIT_LD()      asm volatile("tcgen05.wait::ld.sync.aligned;" ::: "memory")
#define FENCE_PROXY_ASYNC()    asm volatile("fence.proxy.async.shared::cta;" ::: "memory")
#define MBARRIER_INIT(mb, c) \
    asm volatile("mbarrier.init.shared.b64 [%0], %1;" :: "r"((uint32_t)(mb)), "r"((uint32_t)(c)) : "memory")
#define MBARRIER_WAIT_PARITY(mb, ph) do { \
    uint32_t _m = (uint32_t)(mb), _p = (uint32_t)(ph), _d; \
    asm volatile("{ .reg .pred p; mbarrier.try_wait.parity.acquire.cta.shared::cta.b64 p, [%1], %2; selp.b32 %0, 1, 0, p; }" \
                 : "=r"(_d) : "r"(_m), "r"(_p) : "memory"); \
    if (!_d) { \
        asm volatile("{ .reg .pred P1; WL_%=: mbarrier.try_wait.parity.acquire.cta.shared::cta.b64 P1, [%0], %1, 0x989680; @P1 bra.uni WD_%=; bra.uni WL_%=; WD_%=: }" \
                     :: "r"(_m), "r"(_p) : "memory"); \
    } } while (0)

#define TCGEN05_LD_32X32B_X32(r, addr) \
    asm volatile("tcgen05.ld.sync.aligned.32x32b.x32.b32 " \
        "{%0, %1, %2, %3, %4, %5, %6, %7, %8, %9, %10, %11, %12, %13, %14, %15, " \
        " %16, %17, %18, %19, %20, %21, %22, %23, %24, %25, %26, %27, %28, %29, %30, %31}, [%32];" \
        : "=r"((r)[0]),  "=r"((r)[1]),  "=r"((r)[2]),  "=r"((r)[3]), \
          "=r"((r)[4]),  "=r"((r)[5]),  "=r"((r)[6]),  "=r"((r)[7]), \
          "=r"((r)[8]),  "=r"((r)[9]),  "=r"((r)[10]), "=r"((r)[11]), \
          "=r"((r)[12]), "=r"((r)[13]), "=r"((r)[14]), "=r"((r)[15]), \
          "=r"((r)[16]), "=r"((r)[17]), "=r"((r)[18]), "=r"((r)[19]), \
          "=r"((r)[20]), "=r"((r)[21]), "=r"((r)[22]), "=r"((r)[23]), \
          "=r"((r)[24]), "=r"((r)[25]), "=r"((r)[26]), "=r"((r)[27]), \
          "=r"((r)[28]), "=r"((r)[29]), "=r"((r)[30]), "=r"((r)[31]) \
        : "r"(addr))

__device__ __forceinline__ void mma_tf32_ss(uint32_t d, uint64_t ad, uint64_t bd,
                                            uint32_t idesc, bool acc) {
    uint32_t en = acc ? 1u : 0u, z = 0u;
    asm volatile(
        "{\n\t.reg .pred p;\n\tsetp.ne.u32 p, %6, 0;\n\t"
        "tcgen05.mma.cta_group::1.kind::tf32 [%0], %1, %2, %3, {%4, %4, %4, %4}, p;\n\t}"
        :: "r"(d), "l"(ad), "l"(bd), "r"(idesc), "r"(z), "r"(z), "r"(en) : "memory");
}
#endif  // HAS_TCGEN05

// ---------------- weight packing (SIMT fallback pass only needs these) --------
__global__ void pack_weights_k(const float* __restrict__ wl, const float* __restrict__ ul,
                               const float* __restrict__ wr, const float* __restrict__ ur) {
    int idx = blockIdx.x * blockDim.x + threadIdx.x;
    if (idx >= KD * JD) return;
    int k = idx / JD, j = idx % JD;
    g_wlt[idx] = (j < 1536) ? wl[(size_t)j * KD + k] : ul[(size_t)(j - 1536) * KD + k];
    g_wrt[idx] = (j < 1536) ? wr[(size_t)j * KD + k] : ur[(size_t)(j - 1536) * KD + k];
}

// ---------------- level decomposition ----------------------------------------
__global__ void build_levels_k(const int* __restrict__ parent) {
    int tid = threadIdx.x;
    if (tid < NNODE) { g_count[tid] = 0; g_cursor[tid] = 0; g_icount[tid] = 0; g_icursor[tid] = 0; }
    if (tid == 0) g_nlev = 0;
    __syncthreads();
    if (tid < BB) {
        int base = tid * NNODE;
        for (int t = 0; t < NNODE; t++) g_haschild[base + t] = 0;
    }
    __syncthreads();
    if (tid < BB) {
        int base = tid * NNODE;
        g_lvl[base] = 0;
        atomicAdd(&g_count[0], 1);
        int mx = 0;
        for (int t = 1; t < NNODE; t++) {
            int p = parent[base + t];          // guaranteed p < t
            int L = (int)g_lvl[base + p] + 1;
            g_lvl[base + t] = (unsigned short)L;
            atomicAdd(&g_count[L], 1);
            g_haschild[base + p] = 1;
            if (L > mx) mx = L;
        }
        atomicMax(&g_nlev, mx + 1);
    }
    __syncthreads();
    if (tid < BB) {
        int base = tid * NNODE;
        for (int t = 0; t < NNODE; t++)
            if (g_haschild[base + t]) atomicAdd(&g_icount[g_lvl[base + t]], 1);
    }
    __syncthreads();
    if (tid == 0) {
        int s = 0, si = 0;
        for (int l = 0; l < NNODE; l++) {
            g_off[l] = s;  s  += g_count[l];
            g_ioff[l] = si; si += g_icount[l];
        }
        g_off[NNODE] = s; g_ioff[NNODE] = si;
    }
    __syncthreads();
    if (tid < BB) {
        int base = tid * NNODE;
        for (int t = 0; t < NNODE; t++) {
            int L = g_lvl[base + t];
            int pos = g_off[L] + atomicAdd(&g_cursor[L], 1);
            g_nodeid[pos] = (unsigned)(base + t);
            g_parid[pos]  = (t == 0) ? -1 : (base + parent[base + t]);
            if (g_haschild[base + t]) {
                int ip = g_ioff[L] + atomicAdd(&g_icursor[L], 1);
                g_iwork[ip] = base + t;
            }
        }
    }
}

// ---------------- SIMT GEMM tile (fallback pass only) -------------------------
#if !HAS_TCGEN05
template<bool GATHER, int NT>
__device__ __forceinline__ void gemm_tile(
    const float* Asrc, const int* rows, int M,
    const float* __restrict__ Bt, float* Cout, const int* outrows, int tm, int tn) {
    __shared__ float As[BKT][BM + 4];
    __shared__ float Bs[BKT][BN];
    int tid = threadIdx.x;
    if (tid >= 256) { for (int k0 = 0; k0 < KD; k0 += BKT) { __syncthreads(); __syncthreads(); } return; }
    int tx = tid & 15, ty = tid >> 4;
    int row0 = tm * BM, col0 = tn * BN;

    float acc[4][8];
#pragma unroll
    for (int m = 0; m < 4; m++)
#pragma unroll
        for (int n = 0; n < 8; n++) acc[m][n] = 0.f;

    int arow = tid >> 2;
    int akq  = (tid & 3) * 4;
    const float* aptr = nullptr;
    {
        int r = row0 + arow;
        if (GATHER) {
            int p = (r < M) ? rows[r] : -1;
            if (p >= 0) aptr = Asrc + (size_t)p * KD;
        } else {
            if (r < M) aptr = Asrc + (size_t)r * KD;
        }
    }

    for (int k0 = 0; k0 < KD; k0 += BKT) {
        float4 av = make_float4(0.f, 0.f, 0.f, 0.f);
        if (aptr) av = *(const float4*)(aptr + k0 + akq);
        As[akq + 0][arow] = av.x;
        As[akq + 1][arow] = av.y;
        As[akq + 2][arow] = av.z;
        As[akq + 3][arow] = av.w;
#pragma unroll
        for (int i = 0; i < 2; i++) {
            int f  = tid + i * 256;
            int bk = f >> 5;
            int c4 = (f & 31) * 4;
            *(float4*)&Bs[bk][c4] = *(const float4*)(Bt + (size_t)(k0 + bk) * JD + col0 + c4);
        }
        __syncthreads();
#pragma unroll
        for (int k = 0; k < BKT; k++) {
            float a[4], b[8];
            *(float4*)a       = *(const float4*)&As[k][ty * 4];
            *(float4*)b       = *(const float4*)&Bs[k][tx * 8];
            *(float4*)(b + 4) = *(const float4*)&Bs[k][tx * 8 + 4];
#pragma unroll
            for (int m = 0; m < 4; m++)
#pragma unroll
                for (int n = 0; n < 8; n++) acc[m][n] = fmaf(a[m], b[n], acc[m][n]);
        }
        __syncthreads();
    }

#pragma unroll
    for (int m = 0; m < 4; m++) {
        int r = row0 + ty * 4 + m;
        if (r < M) {
            int orow = outrows ? outrows[r] : r;
            float* cp = Cout + (size_t)orow * JD + col0 + tx * 8;
            *(float4*)cp       = make_float4(acc[m][0], acc[m][1], acc[m][2], acc[m][3]);
            *(float4*)(cp + 4) = make_float4(acc[m][4], acc[m][5], acc[m][6], acc[m][7]);
        }
    }
}
#endif

// ---------------- LEFT projection GEMM ----------------------------------------
// out[node, j] = sum_k emb[node,k] * W[j,k], W rows = wl (j<1536) / ul (j>=1536).
__global__ __launch_bounds__(256, 2) void left_tc_k(const float* __restrict__ emb,
                                                    const float* __restrict__ wl,
                                                    const float* __restrict__ ul) {
#if HAS_TCGEN05
    __shared__ char rawbuf[2 * LTM * 128 + 1024];   // A tile + B tile, 1024B-aligned
    __shared__ uint32_t s_tmem;
    __shared__ __align__(8) unsigned long long s_mbar;

    int tid = threadIdx.x;
    int wid = tid >> 5, lane = tid & 31;
    int row0 = blockIdx.y * LTM;      // node rows
    int col0 = blockIdx.x * LTN;      // j cols

    uint32_t raw = smem_u32(rawbuf);
    uint32_t aBase = (raw + 1023u) & ~1023u;
    uint32_t bBase = aBase + LTM * 128;
    char* aPtr = rawbuf + (aBase - raw);
    char* bPtr = aPtr + LTM * 128;
    uint32_t mb = smem_u32(&s_mbar);
    uint32_t tp = smem_u32(&s_tmem);

    if (wid == 0) { TCGEN05_ALLOC(tp, 128); TCGEN05_RELINQ(); }
    if (tid == 0) MBARRIER_INIT(mb, 1);
    __syncthreads();
    uint32_t tmem;
    asm volatile("ld.shared.b32 %0, [%1];" : "=r"(tmem) : "r"(tp));

    uint64_t ad = MAKE_SMEM_DESC(aBase);
    uint64_t bd = MAKE_SMEM_DESC(bBase);

    for (int c = 0; c < LCHUNKS; c++) {
        if (c > 0) MBARRIER_WAIT_PARITY(mb, (c - 1) & 1);   // prior MMA done reading SMEM
        int kc0 = c * LKC;
#pragma unroll
        for (int i = 0; i < 4; i++) {
            int f = tid + (i << 8);
            int row = f >> 3, seg = f & 7;
            float4 v = *(const float4*)(emb + (size_t)(row0 + row) * KD + kc0 + seg * 4);
            uint4 t = make_uint4(to_tf32(v.x), to_tf32(v.y), to_tf32(v.z), to_tf32(v.w));
            *(uint4*)(aPtr + SMEM_SWIZZLE_128B(row * 128 + seg * 16)) = t;
        }
#pragma unroll
        for (int i = 0; i < 4; i++) {
            int f = tid + (i << 8);
            int row = f >> 3, seg = f & 7;
            int j = col0 + row;
            const float* src = (j < 1536) ? (wl + (size_t)j * KD) : (ul + (size_t)(j - 1536) * KD);
            float4 v = *(const float4*)(src + kc0 + seg * 4);
            uint4 t = make_uint4(to_tf32(v.x), to_tf32(v.y), to_tf32(v.z), to_tf32(v.w));
            *(uint4*)(bPtr + SMEM_SWIZZLE_128B(row * 128 + seg * 16)) = t;
        }
        __syncthreads();
        FENCE_PROXY_ASYNC();
        if (wid == 0) {
            if (elect_one_pred()) {
#pragma unroll
                for (int s = 0; s < 4; s++)   // 4 K-steps of 8 tf32 (32B desc stride = +2)
                    mma_tf32_ss(tmem, ad + s * 2, bd + s * 2, LIDESC, (c > 0) || (s > 0));
                TCGEN05_COMMIT(mb);
            }
        }
    }
    MBARRIER_WAIT_PARITY(mb, (LCHUNKS - 1) & 1);
    TCGEN05_FENCE_AFTER();

    if (wid < 4) {
        int r = row0 + wid * 32 + lane;
        float* dst0 = g_left + (size_t)r * JD + col0;
#pragma unroll
        for (int cb = 0; cb < LTN; cb += 32) {
            uint32_t d[32];
            TCGEN05_LD_32X32B_X32(d, tmem + cb);
            TCGEN05_WAIT_LD();
#pragma unroll
            for (int j = 0; j < 32; j++) dst0[cb + j] = __uint_as_float(d[j]);
        }
        TCGEN05_FENCE_BEFORE();
    }
    __syncthreads();
    if (wid == 0) TCGEN05_DEALLOC(tmem, 128);
#else
    for (int half = 0; half < 2; half++) {
        int rowbase = blockIdx.y * LTM + half * BM;
        gemm_tile<false, 256>(emb + (size_t)rowbase * KD, nullptr, BM, g_wlt,
                              g_left + (size_t)rowbase * JD, nullptr, 0, blockIdx.x);
        __syncthreads();
    }
#endif
}

// ---------------- grid barrier ----------------------------------------------
__device__ __forceinline__ void grid_barrier(unsigned target) {
    __syncthreads();
    if (threadIdx.x == 0) {
        __threadfence();
        unsigned arrived = atomicAdd(&g_bar_count, 1);
        if (arrived == gridDim.x - 1) {
            atomicExch(&g_bar_count, 0);
            __threadfence();
            atomicExch(&g_bar_epoch, target);
        } else {
            while (atomicAdd(&g_bar_epoch, 0u) < target) { __nanosleep(64); }
        }
    }
    __syncthreads();
}

// ---------------- persistent level-sweep kernel -------------------------------
// Per level L: (A) epilogue for all L-nodes (reads g_rw[parent], computed when the
// parent's level ran phase B); (B) right-GEMM (tcgen05 tf32) for INTERNAL
// L-nodes only: g_rw[nid] = h[nid] @ Wright^T (dedup: one row per parent).
__global__ __launch_bounds__(TLB) void tree_lstm_k(float* hout,
                                                   const float* __restrict__ wo,
                                                   const float* __restrict__ bias,
                                                   const float* __restrict__ wr,
                                                   const float* __restrict__ ur) {
    __shared__ float pooled_s[TLB / 32][24];
    unsigned epoch = g_bar_epoch;   // carries across graph replays; uniform at entry
    int nlev = g_nlev;
    int tid  = threadIdx.x;
    int warp = tid >> 5, lane = tid & 31;
    int gw = blockIdx.x * (TLB / 32) + warp;
    int nw = gridDim.x * (TLB / 32);

#if HAS_TCGEN05
    __shared__ char rawbuf[2 * LTM * 128 + 1024];
    __shared__ uint32_t s_tmem;
    __shared__ __align__(8) unsigned long long s_mbar;
    uint32_t raw = smem_u32(rawbuf);
    uint32_t aBase = (raw + 1023u) & ~1023u;
    uint32_t bBase = aBase + LTM * 128;
    char* aPtr = rawbuf + (aBase - raw);
    char* bPtr = aPtr + LTM * 128;
    uint32_t mb = smem_u32(&s_mbar);
    uint32_t tp = smem_u32(&s_tmem);
    if (warp == 0) { TCGEN05_ALLOC(tp, 128); TCGEN05_RELINQ(); }
    if (tid == 0) MBARRIER_INIT(mb, 1);
    __syncthreads();
    uint32_t tmem;
    asm volatile("ld.shared.b32 %0, [%1];" : "=r"(tmem) : "r"(tp));
    uint64_t ad = MAKE_SMEM_DESC(aBase);
    uint64_t bd = MAKE_SMEM_DESC(bBase);
    int commits = 0;
#endif

    for (int lvl = 0; lvl < nlev; lvl++) {
        int base = g_off[lvl];
        int M    = g_off[lvl + 1] - base;

        // ---------------- Phase A: per-node epilogue (warp per node) ----------
        for (int i = gw; i < M; i += nw) {
            unsigned nid = g_nodeid[base + i];
            int pidx = g_parid[base + i];
            const float* Lrow = g_left + (size_t)nid * JD;

            if (pidx >= 0) {
                const float* Rrow = g_rw + (size_t)pidx * JD;
#pragma unroll
                for (int gp = 0; gp < 24; gp++) {
                    int o = gp * 64 + lane;
                    float v = Lrow[o] * Rrow[o] + Lrow[o + 32] * Rrow[o + 32];
#pragma unroll
                    for (int s = 16; s > 0; s >>= 1) v += __shfl_xor_sync(0xffffffffu, v, s);
                    if (lane == 0) pooled_s[warp][gp] = v;
                }
                __syncwarp();
                for (int hh = lane; hh < HD; hh += 32) {
                    float gv[3];
#pragma unroll
                    for (int g = 0; g < 3; g++) {
                        float acc = bias[g * HD + hh] + Lrow[1536 + g * HD + hh]
                                  + Rrow[1536 + g * HD + hh];
                        const float* wop = wo + (size_t)(g * HD + hh) * 8;
#pragma unroll
                        for (int p = 0; p < 8; p++) acc = fmaf(pooled_s[warp][g * 8 + p], wop[p], acc);
                        gv[g] = acc;
                    }
                    float f  = 1.f / (1.f + expf(-gv[0]));
                    float o_ = 1.f / (1.f + expf(-gv[1]));
                    float z  = tanhf(gv[2]);
                    float pc = g_c[(size_t)pidx * HD + hh];
                    float c  = pc * f + (1.f - f) * z;
                    float h  = o_ * tanhf(c);
                    g_c[(size_t)nid * HD + hh]  = c;
                    hout[(size_t)nid * HD + hh] = h;
                }
                __syncwarp();   // pooled_s reuse
            } else {
                // root: parent h == 0 -> pooled = 0, right-linear = 0, pc = 0
                for (int hh = lane; hh < HD; hh += 32) {
                    float gv[3];
#pragma unroll
                    for (int g = 0; g < 3; g++)
                        gv[g] = bias[g * HD + hh] + Lrow[1536 + g * HD + hh];
                    float f  = 1.f / (1.f + expf(-gv[0]));
                    float o_ = 1.f / (1.f + expf(-gv[1]));
                    float z  = tanhf(gv[2]);
                    float c  = (1.f - f) * z;
                    float h  = o_ * tanhf(c);
                    g_c[(size_t)nid * HD + hh]  = c;
                    hout[(size_t)nid * HD + hh] = h;
                }
            }
        }
        epoch++; grid_barrier(epoch);

        // ---------------- Phase B: right-GEMM for internal nodes --------------
        int ibase = g_ioff[lvl];
        int Mi    = g_ioff[lvl + 1] - ibase;
        if (Mi > 0) {
#if HAS_TCGEN05
            int ntm = (Mi + LTM - 1) / LTM;
            int ntiles = ntm * NTN;
            for (int tile = blockIdx.x; tile < ntiles; tile += gridDim.x) {
                int tm = tile / NTN, tn = tile % NTN;
                int row0 = tm * LTM, col0 = tn * LTN;
                for (int c = 0; c < LCHUNKS; c++) {
                    if (commits > 0) MBARRIER_WAIT_PARITY(mb, (commits - 1) & 1);
                    int kc0 = c * LKC;
                    // A: gathered h rows (tf32, SW128); rows >= Mi -> zeros
#pragma unroll
                    for (int i = 0; i < 2; i++) {
                        int f = tid + (i << 9);
                        int row = f >> 3, seg = f & 7;
                        int r = row0 + row;
                        float4 v = make_float4(0.f, 0.f, 0.f, 0.f);
                        if (r < Mi)
                            v = *(const float4*)(hout + (size_t)g_iwork[ibase + r] * KD + kc0 + seg * 4);
                        uint4 t = make_uint4(to_tf32(v.x), to_tf32(v.y), to_tf32(v.z), to_tf32(v.w));
                        *(uint4*)(aPtr + SMEM_SWIZZLE_128B(row * 128 + seg * 16)) = t;
                    }
                    // B: Wright rows j = col0+row from wr/ur
#pragma unroll
                    for (int i = 0; i < 2; i++) {
                        int f = tid + (i << 9);
                        int row = f >> 3, seg = f & 7;
                        int j = col0 + row;
                        const float* src = (j < 1536) ? (wr + (size_t)j * KD)
                                                      : (ur + (size_t)(j - 1536) * KD);
                        float4 v = *(const float4*)(src + kc0 + seg * 4);
                        uint4 t = make_uint4(to_tf32(v.x), to_tf32(v.y), to_tf32(v.z), to_tf32(v.w));
                        *(uint4*)(bPtr + SMEM_SWIZZLE_128B(row * 128 + seg * 16)) = t;
                    }
                    __syncthreads();
                    FENCE_PROXY_ASYNC();
                    if (warp == 0) {
                        if (elect_one_pred()) {
#pragma unroll
                            for (int s = 0; s < 4; s++)
                                mma_tf32_ss(tmem, ad + s * 2, bd + s * 2, LIDESC, (c > 0) || (s > 0));
                            TCGEN05_COMMIT(mb);
                        }
                    }
                    commits++;
                }
                MBARRIER_WAIT_PARITY(mb, (commits - 1) & 1);
                TCGEN05_FENCE_AFTER();
                if (warp < 4) {
                    int r = row0 + warp * 32 + lane;
                    float* dst0 = (r < Mi) ? (g_rw + (size_t)g_iwork[ibase + r] * JD + col0) : nullptr;
#pragma unroll
                    for (int cb = 0; cb < LTN; cb += 32) {
                        uint32_t d[32];
                        TCGEN05_LD_32X32B_X32(d, tmem + cb);
                        TCGEN05_WAIT_LD();
                        if (dst0) {
#pragma unroll
                            for (int j = 0; j < 32; j++) dst0[cb + j] = __uint_as_float(d[j]);
                        }
                    }
                    TCGEN05_FENCE_BEFORE();
                }
                __syncthreads();   // TMEM reads done before next tile's MMA overwrites D
            }
#else
            int ntiles = ((Mi + BM - 1) / BM) * (JD / BN);
            for (int tile = blockIdx.x; tile < ntiles; tile += gridDim.x) {
                gemm_tile<true, TLB>(hout, g_iwork + ibase, Mi, g_wrt,
                                     g_rw, g_iwork + ibase, tile / (JD / BN), tile % (JD / BN));
            }
#endif
        }
        epoch++; grid_barrier(epoch);
    }
#if HAS_TCGEN05
    __syncthreads();
    if (warp == 0) TCGEN05_DEALLOC(tmem, 128);
#endif
}

// ---------------- launch ------------------------------------------------------
extern "C" void kernel_launch(void* const* d_in, const int* in_sizes, int n_in,
                              void* d_out, int out_size) {
    const float* emb    = (const float*)d_in[0];
    const int*   parent = (const int*)d_in[1];
    // d_in[2] = node_mask (unused, all ones)
    const float* wl   = (const float*)d_in[3];
    const float* wr   = (const float*)d_in[4];
    const float* wo   = (const float*)d_in[5];
    const float* ul   = (const float*)d_in[6];
    const float* ur   = (const float*)d_in[7];
    const float* bias = (const float*)d_in[8];
    float* hout = (float*)d_out;

    pack_weights_k<<<(KD * JD + 255) / 256, 256>>>(wl, ul, wr, ur);
    build_levels_k<<<1, 512>>>(parent);
    left_tc_k<<<dim3(JD / LTN, NTOT / LTM), 256>>>(emb, wl, ul);
    tree_lstm_k<<<NCTA, TLB>>>(hout, wo, bias, wr, ur);
}